// round 12
// baseline (speedup 1.0000x reference)
#include <cuda_runtime.h>
#include <cuda_fp16.h>
#include <cstdint>

#define N_T   21
#define SEQ   1024
#define DIMC  3072
#define NH    24
#define HDIM  128
#define ENCC  768
#define NAK   32
#define NTOK  (N_T * SEQ)          /* 21504 */
#define ENCR  (N_T * NAK)          /* 672 */

// ---------------- scratch (device globals: allocation-free) ----------------
__device__ float g_KV[(size_t)ENCR * 2 * DIMC];
__device__ __align__(16) float g_minmax[4];

__device__ __half g_qh [(size_t)NTOK * DIMC];      // Q fp16 (LN+RoPE applied)
__device__ __half g_xh [(size_t)NTOK * DIMC];      // activations fp16
__device__ __half g_oh [(size_t)NTOK * DIMC];      // attn output fp16
__device__ __half g_eh [(size_t)ENCR * ENCC];
__device__ __half g_wqh[(size_t)DIMC * DIMC];
__device__ __half g_wph[(size_t)DIMC * DIMC];
__device__ __half g_wkh[(size_t)2 * DIMC * ENCC];

// ---------------- conversions ----------------------------------------------
__global__ __launch_bounds__(256) void convert_single_h(
    const float4* __restrict__ in, __half2* __restrict__ out, int n4)
{
    int i = blockIdx.x * 256 + threadIdx.x;
    if (i >= n4) return;
    float4 v = in[i];
    out[2 * i]     = __floats2half2_rn(v.x, v.y);
    out[2 * i + 1] = __floats2half2_rn(v.z, v.w);
}

#define W1N ((DIMC * DIMC) / 4)
#define W2N ((2 * DIMC * ENCC) / 4)
__global__ __launch_bounds__(256) void convert_w3(
    const float4* __restrict__ w1, const float4* __restrict__ w2,
    const float4* __restrict__ w3,
    __half2* __restrict__ o1, __half2* __restrict__ o2, __half2* __restrict__ o3)
{
    int i = blockIdx.x * 256 + threadIdx.x;
    const float4* src; __half2* dst; int j;
    if (i < W1N)              { src = w1; dst = o1; j = i; }
    else if (i < W1N + W2N)   { src = w2; dst = o2; j = i - W1N; }
    else if (i < 2*W1N + W2N) { src = w3; dst = o3; j = i - W1N - W2N; }
    else return;
    float4 v = src[j];
    dst[2 * j]     = __floats2half2_rn(v.x, v.y);
    dst[2 * j + 1] = __floats2half2_rn(v.z, v.w);
}

// ---------------- shared GEMM machinery ------------------------------------
#define ROWB   144                     /* bytes per smem row: 128 data + 16 pad */
#define ARRB   (128 * ROWB)
#define OFF_A  0
#define OFF_B  ARRB
#define STAGEB (2 * ARRB)              /* 36864 B per stage */
#define GEMM_SMEM (3 * STAGEB)         /* 110592 B          */

__device__ __forceinline__ uint32_t smem_u32(const void* p) {
    uint32_t a;
    asm("{ .reg .u64 t; cvta.to.shared.u64 t, %1; cvt.u32.u64 %0, t; }" : "=r"(a) : "l"(p));
    return a;
}
__device__ __forceinline__ void cp16(uint32_t dst, const void* src, unsigned bytes) {
    asm volatile("cp.async.cg.shared.global [%0], [%1], 16, %2;"
                 :: "r"(dst), "l"(src), "r"(bytes) : "memory");
}
__device__ __forceinline__ void ldsm4(unsigned& r0, unsigned& r1, unsigned& r2, unsigned& r3,
                                      uint32_t addr) {
    asm volatile("ldmatrix.sync.aligned.m8n8.x4.shared.b16 {%0,%1,%2,%3}, [%4];"
                 : "=r"(r0), "=r"(r1), "=r"(r2), "=r"(r3) : "r"(addr));
}
__device__ __forceinline__ void mma_f16(float* c, const unsigned* a, unsigned b0, unsigned b1) {
    asm volatile(
        "mma.sync.aligned.m16n8k16.row.col.f32.f16.f16.f32 "
        "{%0,%1,%2,%3}, {%4,%5,%6,%7}, {%8,%9}, {%0,%1,%2,%3};\n"
        : "+f"(c[0]), "+f"(c[1]), "+f"(c[2]), "+f"(c[3])
        : "r"(a[0]), "r"(a[1]), "r"(a[2]), "r"(a[3]), "r"(b0), "r"(b1));
}

#define GEMM_PROLOGUE_AND_MAINLOOP(Aptr, Bptr, Mv, Kv)                          \
    extern __shared__ __align__(128) char smem[];                               \
    uint32_t sb = smem_u32(smem);                                               \
    int tid  = threadIdx.x;                                                     \
    int warp = tid >> 5, lane = tid & 31;                                       \
    int wm = warp >> 1, wn = warp & 1;                                          \
    int quad = lane >> 2, t4 = lane & 3;                                        \
    int m0 = blockIdx.y * 128, n0 = blockIdx.x * 128;                           \
    int nk = (Kv) >> 6;                                                         \
    int rowoff_a = ((lane >> 3) & 1) * 8 + (lane & 7);                          \
    int koff_a   = (lane >> 4) * 16;                                            \
    int rowoff_b = ((lane >> 4) & 1) * 8 + (lane & 7);                          \
    int koff_b   = ((lane >> 3) & 1) * 16;                                      \
    float acc[4][8][4];                                                         \
    _Pragma("unroll")                                                           \
    for (int i = 0; i < 4; i++)                                                 \
        _Pragma("unroll")                                                       \
        for (int j = 0; j < 8; j++)                                             \
            _Pragma("unroll")                                                   \
            for (int c = 0; c < 4; c++) acc[i][j][c] = 0.f;                     \
    auto issue_stage = [&](int kc) {                                            \
        int slot = kc % 3;                                                      \
        uint32_t stb = sb + slot * STAGEB;                                      \
        int kx = kc * 64;                                                       \
        _Pragma("unroll")                                                       \
        for (int j = 0; j < 8; j++) {                                           \
            int chunk = j * 128 + tid;                                          \
            int row = chunk >> 3, kcx = chunk & 7;                              \
            uint32_t doff = row * ROWB + kcx * 16;                              \
            int gm = m0 + row;                                                  \
            int gmc = gm < (Mv) ? gm : (Mv) - 1;                                \
            cp16(stb + OFF_A + doff, (Aptr) + (size_t)gmc * (Kv) + kx + kcx * 8,\
                 gm < (Mv) ? 16u : 0u);                                         \
            cp16(stb + OFF_B + doff, (Bptr) + (size_t)(n0 + row) * (Kv) + kx + kcx * 8, 16u); \
        }                                                                       \
    };                                                                          \
    issue_stage(0);                                                             \
    asm volatile("cp.async.commit_group;" ::: "memory");                        \
    issue_stage(1);                                                             \
    asm volatile("cp.async.commit_group;" ::: "memory");                        \
    for (int kc = 0; kc < nk; kc++) {                                           \
        asm volatile("cp.async.wait_group 1;" ::: "memory");                    \
        __syncthreads();                                                        \
        if (kc + 2 < nk) issue_stage(kc + 2);                                   \
        asm volatile("cp.async.commit_group;" ::: "memory");                    \
        int slot = kc % 3;                                                      \
        uint32_t aBase = sb + slot * STAGEB + OFF_A + (wm * 64 + rowoff_a) * ROWB + koff_a; \
        uint32_t bBase = sb + slot * STAGEB + OFF_B + (wn * 64 + rowoff_b) * ROWB + koff_b; \
        _Pragma("unroll")                                                       \
        for (int ks = 0; ks < 4; ks++) {                                        \
            uint32_t ak = aBase + ks * 32;                                      \
            uint32_t bk = bBase + ks * 32;                                      \
            unsigned a[4][4], b[8][2];                                          \
            _Pragma("unroll")                                                   \
            for (int mi = 0; mi < 4; mi++)                                      \
                ldsm4(a[mi][0], a[mi][1], a[mi][2], a[mi][3], ak + mi * 16 * ROWB); \
            _Pragma("unroll")                                                   \
            for (int nj = 0; nj < 4; nj++)                                      \
                ldsm4(b[nj * 2][0], b[nj * 2][1], b[nj * 2 + 1][0], b[nj * 2 + 1][1], \
                      bk + nj * 16 * ROWB);                                     \
            _Pragma("unroll")                                                   \
            for (int mi = 0; mi < 4; mi++)                                      \
                _Pragma("unroll")                                               \
                for (int ni = 0; ni < 8; ni++)                                  \
                    mma_f16(acc[mi][ni], a[mi], b[ni][0], b[ni][1]);            \
        }                                                                       \
    }

// ---------------- plain GEMM (fp32 out): C = A @ B^T + bias ----------------
__global__ __launch_bounds__(128) void gemm_fp16(
    const __half* __restrict__ A, const __half* __restrict__ B,
    const float* __restrict__ bias, float* __restrict__ C,
    int M, int N, int K)
{
    GEMM_PROLOGUE_AND_MAINLOOP(A, B, M, K)

    #pragma unroll
    for (int mi = 0; mi < 4; mi++) {
        int gm = m0 + wm * 64 + mi * 16 + quad;
        #pragma unroll
        for (int ni = 0; ni < 8; ni++) {
            int gn = n0 + wn * 64 + ni * 8 + t4 * 2;
            float b0v = bias[gn], b1v = bias[gn + 1];
            if (gm < M)
                *(float2*)(C + (size_t)gm * N + gn) =
                    make_float2(acc[mi][ni][0] + b0v, acc[mi][ni][1] + b1v);
            if (gm + 8 < M)
                *(float2*)(C + (size_t)(gm + 8) * N + gn) =
                    make_float2(acc[mi][ni][2] + b0v, acc[mi][ni][3] + b1v);
        }
    }
}

// -------- GEMM1 with fused bias + LayerNorm(1e-6) + RoPE -> g_qh fp16 ------
// M=NTOK, N=DIMC, K=DIMC fixed. One 128-col tile == one head.
__global__ __launch_bounds__(128) void gemm_q_fused(
    const __half* __restrict__ A, const __half* __restrict__ B,
    const float* __restrict__ bias, const float* __restrict__ xmap,
    const float* __restrict__ gamma, const float* __restrict__ beta)
{
    GEMM_PROLOGUE_AND_MAINLOOP(A, B, NTOK, DIMC)

    // ---------------- fused epilogue ----------------
    __syncthreads();
    float* red = (float*)smem;                 // [128 rows][4]: wn0{s,q} wn1{s,q}

    // bias add (q_b)
    #pragma unroll
    for (int ni = 0; ni < 8; ni++) {
        float2 bv = *(const float2*)(bias + n0 + wn * 64 + ni * 8 + t4 * 2);
        #pragma unroll
        for (int mi = 0; mi < 4; mi++) {
            acc[mi][ni][0] += bv.x; acc[mi][ni][1] += bv.y;
            acc[mi][ni][2] += bv.x; acc[mi][ni][3] += bv.y;
        }
    }
    // per-row partial sums over this warp's 64 cols
    #pragma unroll
    for (int mi = 0; mi < 4; mi++) {
        float sA = 0.f, qA = 0.f, sB = 0.f, qB = 0.f;
        #pragma unroll
        for (int ni = 0; ni < 8; ni++) {
            sA += acc[mi][ni][0] + acc[mi][ni][1];
            qA += acc[mi][ni][0] * acc[mi][ni][0] + acc[mi][ni][1] * acc[mi][ni][1];
            sB += acc[mi][ni][2] + acc[mi][ni][3];
            qB += acc[mi][ni][2] * acc[mi][ni][2] + acc[mi][ni][3] * acc[mi][ni][3];
        }
        #pragma unroll
        for (int o = 1; o <= 2; o <<= 1) {
            sA += __shfl_xor_sync(0xffffffffu, sA, o);
            qA += __shfl_xor_sync(0xffffffffu, qA, o);
            sB += __shfl_xor_sync(0xffffffffu, sB, o);
            qB += __shfl_xor_sync(0xffffffffu, qB, o);
        }
        if (t4 == 0) {
            int rA = wm * 64 + mi * 16 + quad, rB = rA + 8;
            red[rA * 4 + wn * 2]     = sA; red[rA * 4 + wn * 2 + 1] = qA;
            red[rB * 4 + wn * 2]     = sB; red[rB * 4 + wn * 2 + 1] = qB;
        }
    }
    __syncthreads();

    const float CF = -0.20762050593046868f;    // -2*log2(10000)/128
    float4 mm = *(const float4*)g_minmax;      // mn0, mx0, mn1, mx1
    int hh = blockIdx.x;                       // head index (N tile == head)

    float2 gv[8], bv2[8]; float fj[8];
    #pragma unroll
    for (int ni = 0; ni < 8; ni++) {
        int i0 = wn * 64 + ni * 8 + t4 * 2;
        gv[ni]  = *(const float2*)(gamma + i0);
        bv2[ni] = *(const float2*)(beta + i0);
        fj[ni]  = exp2f((float)(i0 >> 1) * CF);
    }

    #pragma unroll
    for (int mi = 0; mi < 4; mi++) {
        #pragma unroll
        for (int hf = 0; hf < 2; hf++) {
            int r = wm * 64 + mi * 16 + quad + hf * 8;
            float sum = red[r * 4]     + red[r * 4 + 2];
            float sq  = red[r * 4 + 1] + red[r * 4 + 3];
            float mean = sum * (1.f / HDIM);
            float var  = sq * (1.f / HDIM) - mean * mean;
            float rs   = rsqrtf(var + 1e-6f);

            int tok = m0 + r;
            int bb_ = tok >> 10, ss = tok & 1023;
            int l = (bb_ * (NH * SEQ) + hh * SEQ + ss) % NTOK;
            float map0 = xmap[l], map1 = xmap[NTOK + l];
            float pos = (map0 >= map1) ? (map0 - mm.x) / (mm.y - mm.x) * 4.0f
                                       : (map1 - mm.z) / (mm.w - mm.z) * 4.0f + 20.0f;

            __half2* orow = (__half2*)(g_qh + (size_t)tok * DIMC + n0);
            #pragma unroll
            for (int ni = 0; ni < 8; ni++) {
                int i0 = wn * 64 + ni * 8 + t4 * 2;
                float a0 = acc[mi][ni][hf * 2], a1 = acc[mi][ni][hf * 2 + 1];
                float v0 = (a0 - mean) * rs * gv[ni].x + bv2[ni].x;
                float v1 = (a1 - mean) * rs * gv[ni].y + bv2[ni].y;
                float sn, cs;
                sincosf(pos * fj[ni], &sn, &cs);
                orow[i0 >> 1] = __floats2half2_rn(v0 * cs - v1 * sn, v1 * cs + v0 * sn);
            }
        }
    }
}

// ---------------- min/max of the two x_ref_attn_map rows -------------------
__global__ void minmax_kernel(const float* __restrict__ xmap) {
    int row = blockIdx.x;
    const float* p = xmap + row * NTOK;
    float mn = 3.4e38f, mx = -3.4e38f;
    for (int i = threadIdx.x; i < NTOK; i += blockDim.x) {
        float v = p[i];
        mn = fminf(mn, v); mx = fmaxf(mx, v);
    }
    __shared__ float smn[32], smx[32];
    int lane = threadIdx.x & 31, w = threadIdx.x >> 5;
    #pragma unroll
    for (int o = 16; o; o >>= 1) {
        mn = fminf(mn, __shfl_xor_sync(0xffffffffu, mn, o));
        mx = fmaxf(mx, __shfl_xor_sync(0xffffffffu, mx, o));
    }
    if (lane == 0) { smn[w] = mn; smx[w] = mx; }
    __syncthreads();
    if (w == 0) {
        int nw = blockDim.x >> 5;
        mn = (lane < nw) ? smn[lane] :  3.4e38f;
        mx = (lane < nw) ? smx[lane] : -3.4e38f;
        #pragma unroll
        for (int o = 16; o; o >>= 1) {
            mn = fminf(mn, __shfl_xor_sync(0xffffffffu, mn, o));
            mx = fmaxf(mx, __shfl_xor_sync(0xffffffffu, mx, o));
        }
        if (lane == 0) { g_minmax[row * 2] = mn; g_minmax[row * 2 + 1] = mx; }
    }
}

// ------------- k: LayerNorm(eps 1e-5) + RoPE (pos = 2 or 22) ---------------
__global__ __launch_bounds__(256) void k_ln_rope(const float* __restrict__ gamma,
                                                 const float* __restrict__ beta) {
    int gw   = blockIdx.x * 8 + (threadIdx.x >> 5);
    int lane = threadIdx.x & 31;
    int r = gw / NH;
    int h = gw - r * NH;
    float* row = g_KV + (size_t)r * (2 * DIMC) + h * HDIM;
    float4 v = *(float4*)(row + lane * 4);

    float s  = v.x + v.y + v.z + v.w;
    float sq = v.x * v.x + v.y * v.y + v.z * v.z + v.w * v.w;
    #pragma unroll
    for (int o = 16; o; o >>= 1) {
        s  += __shfl_xor_sync(0xffffffffu, s,  o);
        sq += __shfl_xor_sync(0xffffffffu, sq, o);
    }
    float mean = s * (1.f / HDIM);
    float var  = sq * (1.f / HDIM) - mean * mean;
    float rs   = rsqrtf(var + 1e-5f);

    float4 gg = *(const float4*)(gamma + lane * 4);
    float4 bb = *(const float4*)(beta  + lane * 4);
    v.x = (v.x - mean) * rs * gg.x + bb.x;
    v.y = (v.y - mean) * rs * gg.y + bb.y;
    v.z = (v.z - mean) * rs * gg.z + bb.z;
    v.w = (v.w - mean) * rs * gg.w + bb.w;

    int na = r & (NAK - 1);
    float pos = (na < NAK / 2) ? 2.0f : 22.0f;

    const float CF = -0.20762050593046868f;
    int i0 = lane * 2;
    float f0 = exp2f((float)i0 * CF);
    float f1 = exp2f((float)(i0 + 1) * CF);
    float s0, c0, s1, c1;
    sincosf(pos * f0, &s0, &c0);
    sincosf(pos * f1, &s1, &c1);
    float4 o;
    o.x = v.x * c0 - v.y * s0;
    o.y = v.y * c0 + v.x * s0;
    o.z = v.z * c1 - v.w * s1;
    o.w = v.w * c1 + v.z * s1;
    *(float4*)(row + lane * 4) = o;
}

// ------------- attention: per (b,h), NA=32 keys; fp16 q in, fp16 out -------
#define VPAD 132
__global__ __launch_bounds__(256) void attn_kernel() {
    int bh = blockIdx.x;
    int b = bh / NH, h = bh - b * NH;
    __shared__ float ks[NAK][VPAD], vs[NAK][VPAD];
    int tid = threadIdx.x;
    for (int idx = tid; idx < NAK * HDIM; idx += 256) {
        int n = idx >> 7, d = idx & 127;
        size_t base = (size_t)(b * NAK + n) * (2 * DIMC) + h * HDIM + d;
        ks[n][d] = g_KV[base];
        vs[n][d] = g_KV[base + DIMC];
    }
    __syncthreads();

    int warp = tid >> 5, lane = tid & 31;
    const float SC = 0.08838834764831845f;
    for (int s = warp; s < SEQ; s += 8) {
        const __half2* q = (const __half2*)(g_qh + (size_t)(b * SEQ + s) * DIMC + h * HDIM);
        float sc = 0.f;
        #pragma unroll
        for (int d = 0; d < HDIM; d += 4) {
            float2 q0 = __half22float2(q[d / 2]);
            float2 q1 = __half22float2(q[d / 2 + 1]);
            float4 kv = *(const float4*)(&ks[lane][d]);
            sc += q0.x * kv.x + q0.y * kv.y + q1.x * kv.z + q1.y * kv.w;
        }
        sc *= SC;
        float mx = sc;
        #pragma unroll
        for (int o = 16; o; o >>= 1) mx = fmaxf(mx, __shfl_xor_sync(0xffffffffu, mx, o));
        float e = __expf(sc - mx);
        float sum = e;
        #pragma unroll
        for (int o = 16; o; o >>= 1) sum += __shfl_xor_sync(0xffffffffu, sum, o);
        float p = e / sum;

        float4 acc = make_float4(0.f, 0.f, 0.f, 0.f);
        #pragma unroll
        for (int n = 0; n < NAK; n++) {
            float pn = __shfl_sync(0xffffffffu, p, n);
            float4 vv = *(const float4*)(&vs[n][lane * 4]);
            acc.x += pn * vv.x; acc.y += pn * vv.y;
            acc.z += pn * vv.z; acc.w += pn * vv.w;
        }
        __half2* op = (__half2*)(g_oh + (size_t)(b * SEQ + s) * DIMC + h * HDIM + lane * 4);
        op[0] = __floats2half2_rn(acc.x, acc.y);
        op[1] = __floats2half2_rn(acc.z, acc.w);
    }
}

// ======================= host side =======================
extern "C" void kernel_launch(void* const* d_in, const int* in_sizes, int n_in,
                              void* d_out, int out_size) {
    const float* x     = (const float*)d_in[0];
    const float* enc_i = (const float*)d_in[1];
    const float* xmap  = (const float*)d_in[2];
    const float* q_w   = (const float*)d_in[3];
    const float* q_b   = (const float*)d_in[4];
    const float* kv_w  = (const float*)d_in[5];
    const float* kv_b  = (const float*)d_in[6];
    const float* prj_w = (const float*)d_in[7];
    const float* prj_b = (const float*)d_in[8];
    const float* qn_g  = (const float*)d_in[9];
    const float* qn_b  = (const float*)d_in[10];
    const float* kn_g  = (const float*)d_in[11];
    const float* kn_b  = (const float*)d_in[12];
    float* out = (float*)d_out;

    float *KV;
    __half *xh, *oh, *eh, *wqh, *wph, *wkh;
    cudaGetSymbolAddress((void**)&KV,  g_KV);
    cudaGetSymbolAddress((void**)&xh,  g_xh);
    cudaGetSymbolAddress((void**)&oh,  g_oh);
    cudaGetSymbolAddress((void**)&eh,  g_eh);
    cudaGetSymbolAddress((void**)&wqh, g_wqh);
    cudaGetSymbolAddress((void**)&wph, g_wph);
    cudaGetSymbolAddress((void**)&wkh, g_wkh);

    cudaFuncSetAttribute(gemm_fp16,    cudaFuncAttributeMaxDynamicSharedMemorySize, GEMM_SMEM);
    cudaFuncSetAttribute(gemm_q_fused, cudaFuncAttributeMaxDynamicSharedMemorySize, GEMM_SMEM);

    // L1: x -> fp16
    {
        int n4 = (int)((size_t)NTOK * DIMC / 4);
        convert_single_h<<<(n4 + 255) / 256, 256>>>((const float4*)x, (__half2*)xh, n4);
    }
    // L2: enc -> fp16
    {
        int n4 = (int)((size_t)ENCR * ENCC / 4);
        convert_single_h<<<(n4 + 255) / 256, 256>>>((const float4*)enc_i, (__half2*)eh, n4);
    }
    // L3: all three weights -> fp16 (merged)
    {
        int tot = 2 * W1N + W2N;
        convert_w3<<<(tot + 255) / 256, 256>>>(
            (const float4*)q_w, (const float4*)kv_w, (const float4*)prj_w,
            (__half2*)wqh, (__half2*)wkh, (__half2*)wph);
    }
    // L4: minmax (needed by gemm_q_fused epilogue)
    minmax_kernel<<<2, 256>>>(xmap);

    // L5: GEMM2  KV = enc @ kv_w^T
    gemm_fp16<<<dim3((2 * DIMC) / 128, (ENCR + 127) / 128), 128, GEMM_SMEM>>>(
        eh, wkh, kv_b, KV, ENCR, 2 * DIMC, ENCC);

    // L6 (ncu -s 5 captures this): GEMM1 fused  qh = LN(RoPE(x @ q_w^T + q_b))
    gemm_q_fused<<<dim3(DIMC / 128, NTOK / 128), 128, GEMM_SMEM>>>(
        xh, wqh, q_b, xmap, qn_g, qn_b);

    // L7: k LN + RoPE
    k_ln_rope<<<(ENCR * NH) / 8, 256>>>(kn_g, kn_b);

    // L8: attention
    attn_kernel<<<N_T * NH, 256>>>();

    // L9: GEMM3  out = attn_out @ prj_w^T
    gemm_fp16<<<dim3(DIMC / 128, NTOK / 128), 128, GEMM_SMEM>>>(
        oh, wph, prj_b, out, NTOK, DIMC, DIMC);
}

// round 13
// speedup vs baseline: 1.5302x; 1.5302x over previous
#include <cuda_runtime.h>
#include <cuda_fp16.h>
#include <cstdint>

#define N_T   21
#define SEQ   1024
#define DIMC  3072
#define NH    24
#define HDIM  128
#define ENCC  768
#define NAK   32
#define NTOK  (N_T * SEQ)          /* 21504 */
#define ENCR  (N_T * NAK)          /* 672 */

// ---------------- scratch (device globals: allocation-free) ----------------
__device__ float g_KV[(size_t)ENCR * 2 * DIMC];
__device__ __align__(16) float g_minmax[4];

__device__ __half g_qh [(size_t)NTOK * DIMC];      // Q fp16 (GEMM1 out, LN/RoPE in-place)
__device__ __half g_xh [(size_t)NTOK * DIMC];      // activations fp16
__device__ __half g_oh [(size_t)NTOK * DIMC];      // attn output fp16
__device__ __half g_eh [(size_t)ENCR * ENCC];
__device__ __half g_wqh[(size_t)DIMC * DIMC];
__device__ __half g_wph[(size_t)DIMC * DIMC];
__device__ __half g_wkh[(size_t)2 * DIMC * ENCC];

// ---------------- conversions ----------------------------------------------
__global__ __launch_bounds__(256) void convert_single_h(
    const float4* __restrict__ in, __half2* __restrict__ out, int n4)
{
    int i = blockIdx.x * 256 + threadIdx.x;
    if (i >= n4) return;
    float4 v = in[i];
    out[2 * i]     = __floats2half2_rn(v.x, v.y);
    out[2 * i + 1] = __floats2half2_rn(v.z, v.w);
}

#define W1N ((DIMC * DIMC) / 4)
#define W2N ((2 * DIMC * ENCC) / 4)
__global__ __launch_bounds__(256) void convert_w3(
    const float4* __restrict__ w1, const float4* __restrict__ w2,
    const float4* __restrict__ w3,
    __half2* __restrict__ o1, __half2* __restrict__ o2, __half2* __restrict__ o3)
{
    int i = blockIdx.x * 256 + threadIdx.x;
    const float4* src; __half2* dst; int j;
    if (i < W1N)              { src = w1; dst = o1; j = i; }
    else if (i < W1N + W2N)   { src = w2; dst = o2; j = i - W1N; }
    else if (i < 2*W1N + W2N) { src = w3; dst = o3; j = i - W1N - W2N; }
    else return;
    float4 v = src[j];
    dst[2 * j]     = __floats2half2_rn(v.x, v.y);
    dst[2 * j + 1] = __floats2half2_rn(v.z, v.w);
}

// ---------------- fp16 GEMM: C = A[M,K] @ B[N,K]^T + bias ------------------
// CTA 128x128, BK=64, 3-stage cp.async, 4 warps (64x64 warp tile), ldmatrix.
#define ROWB   144                     /* bytes per smem row: 128 data + 16 pad */
#define ARRB   (128 * ROWB)
#define OFF_A  0
#define OFF_B  ARRB
#define STAGEB (2 * ARRB)              /* 36864 B per stage */
#define GEMM_SMEM (3 * STAGEB)         /* 110592 B          */

__device__ __forceinline__ uint32_t smem_u32(const void* p) {
    uint32_t a;
    asm("{ .reg .u64 t; cvta.to.shared.u64 t, %1; cvt.u32.u64 %0, t; }" : "=r"(a) : "l"(p));
    return a;
}
__device__ __forceinline__ void cp16(uint32_t dst, const void* src, unsigned bytes) {
    asm volatile("cp.async.cg.shared.global [%0], [%1], 16, %2;"
                 :: "r"(dst), "l"(src), "r"(bytes) : "memory");
}
__device__ __forceinline__ void ldsm4(unsigned& r0, unsigned& r1, unsigned& r2, unsigned& r3,
                                      uint32_t addr) {
    asm volatile("ldmatrix.sync.aligned.m8n8.x4.shared.b16 {%0,%1,%2,%3}, [%4];"
                 : "=r"(r0), "=r"(r1), "=r"(r2), "=r"(r3) : "r"(addr));
}
__device__ __forceinline__ void mma_f16(float* c, const unsigned* a, unsigned b0, unsigned b1) {
    asm volatile(
        "mma.sync.aligned.m16n8k16.row.col.f32.f16.f16.f32 "
        "{%0,%1,%2,%3}, {%4,%5,%6,%7}, {%8,%9}, {%0,%1,%2,%3};\n"
        : "+f"(c[0]), "+f"(c[1]), "+f"(c[2]), "+f"(c[3])
        : "r"(a[0]), "r"(a[1]), "r"(a[2]), "r"(a[3]), "r"(b0), "r"(b1));
}

__device__ __forceinline__ void store_pair(float* p, float a, float b) {
    *(float2*)p = make_float2(a, b);
}
__device__ __forceinline__ void store_pair(__half* p, float a, float b) {
    *(__half2*)p = __floats2half2_rn(a, b);
}

template <typename TO>
__global__ __launch_bounds__(128) void gemm_fp16(
    const __half* __restrict__ A, const __half* __restrict__ B,
    const float* __restrict__ bias, TO* __restrict__ C,
    int M, int N, int K)
{
    extern __shared__ __align__(128) char smem[];
    uint32_t sb = smem_u32(smem);

    int tid  = threadIdx.x;
    int warp = tid >> 5, lane = tid & 31;
    int wm = warp >> 1, wn = warp & 1;           // 2x2 warps; warp tile 64x64
    int quad = lane >> 2, t4 = lane & 3;
    int m0 = blockIdx.y * 128, n0 = blockIdx.x * 128;
    int nk = K >> 6;

    int rowoff_a = ((lane >> 3) & 1) * 8 + (lane & 7);
    int koff_a   = (lane >> 4) * 16;
    int rowoff_b = ((lane >> 4) & 1) * 8 + (lane & 7);
    int koff_b   = ((lane >> 3) & 1) * 16;

    float acc[4][8][4];
    #pragma unroll
    for (int i = 0; i < 4; i++)
        #pragma unroll
        for (int j = 0; j < 8; j++)
            #pragma unroll
            for (int c = 0; c < 4; c++) acc[i][j][c] = 0.f;

    auto issue_stage = [&](int kc) {
        int slot = kc % 3;
        uint32_t stb = sb + slot * STAGEB;
        int kx = kc * 64;
        #pragma unroll
        for (int j = 0; j < 8; j++) {
            int chunk = j * 128 + tid;           // 0..1023
            int row = chunk >> 3, kcx = chunk & 7;
            uint32_t doff = row * ROWB + kcx * 16;
            int gm = m0 + row;
            int gmc = gm < M ? gm : M - 1;
            cp16(stb + OFF_A + doff, A + (size_t)gmc * K + kx + kcx * 8,
                 gm < M ? 16u : 0u);
            cp16(stb + OFF_B + doff, B + (size_t)(n0 + row) * K + kx + kcx * 8, 16u);
        }
    };

    issue_stage(0);
    asm volatile("cp.async.commit_group;" ::: "memory");
    issue_stage(1);
    asm volatile("cp.async.commit_group;" ::: "memory");

    for (int kc = 0; kc < nk; kc++) {
        asm volatile("cp.async.wait_group 1;" ::: "memory");
        __syncthreads();
        if (kc + 2 < nk) issue_stage(kc + 2);
        asm volatile("cp.async.commit_group;" ::: "memory");

        int slot = kc % 3;
        uint32_t aBase = sb + slot * STAGEB + OFF_A + (wm * 64 + rowoff_a) * ROWB + koff_a;
        uint32_t bBase = sb + slot * STAGEB + OFF_B + (wn * 64 + rowoff_b) * ROWB + koff_b;

        #pragma unroll
        for (int ks = 0; ks < 4; ks++) {
            uint32_t ak = aBase + ks * 32;
            uint32_t bk = bBase + ks * 32;
            unsigned a[4][4], b[8][2];
            #pragma unroll
            for (int mi = 0; mi < 4; mi++)
                ldsm4(a[mi][0], a[mi][1], a[mi][2], a[mi][3], ak + mi * 16 * ROWB);
            #pragma unroll
            for (int nj = 0; nj < 4; nj++)
                ldsm4(b[nj * 2][0], b[nj * 2][1], b[nj * 2 + 1][0], b[nj * 2 + 1][1],
                      bk + nj * 16 * ROWB);
            #pragma unroll
            for (int mi = 0; mi < 4; mi++)
                #pragma unroll
                for (int ni = 0; ni < 8; ni++)
                    mma_f16(acc[mi][ni], a[mi], b[ni][0], b[ni][1]);
        }
    }

    #pragma unroll
    for (int mi = 0; mi < 4; mi++) {
        int gm = m0 + wm * 64 + mi * 16 + quad;
        #pragma unroll
        for (int ni = 0; ni < 8; ni++) {
            int gn = n0 + wn * 64 + ni * 8 + t4 * 2;
            float b0v = bias[gn], b1v = bias[gn + 1];
            if (gm < M)
                store_pair(C + (size_t)gm * N + gn,
                           acc[mi][ni][0] + b0v, acc[mi][ni][1] + b1v);
            if (gm + 8 < M)
                store_pair(C + (size_t)(gm + 8) * N + gn,
                           acc[mi][ni][2] + b0v, acc[mi][ni][3] + b1v);
        }
    }
}

// ---------------- min/max of the two x_ref_attn_map rows -------------------
__global__ void minmax_kernel(const float* __restrict__ xmap) {
    int row = blockIdx.x;
    const float* p = xmap + row * NTOK;
    float mn = 3.4e38f, mx = -3.4e38f;
    for (int i = threadIdx.x; i < NTOK; i += blockDim.x) {
        float v = p[i];
        mn = fminf(mn, v); mx = fmaxf(mx, v);
    }
    __shared__ float smn[32], smx[32];
    int lane = threadIdx.x & 31, w = threadIdx.x >> 5;
    #pragma unroll
    for (int o = 16; o; o >>= 1) {
        mn = fminf(mn, __shfl_xor_sync(0xffffffffu, mn, o));
        mx = fmaxf(mx, __shfl_xor_sync(0xffffffffu, mx, o));
    }
    if (lane == 0) { smn[w] = mn; smx[w] = mx; }
    __syncthreads();
    if (w == 0) {
        int nw = blockDim.x >> 5;
        mn = (lane < nw) ? smn[lane] :  3.4e38f;
        mx = (lane < nw) ? smx[lane] : -3.4e38f;
        #pragma unroll
        for (int o = 16; o; o >>= 1) {
            mn = fminf(mn, __shfl_xor_sync(0xffffffffu, mn, o));
            mx = fmaxf(mx, __shfl_xor_sync(0xffffffffu, mx, o));
        }
        if (lane == 0) { g_minmax[row * 2] = mn; g_minmax[row * 2 + 1] = mx; }
    }
}

// ------------- q: LayerNorm(eps 1e-6) + RoPE, fp16 in/out ------------------
__global__ __launch_bounds__(256) void ln_rope_q(const float* __restrict__ xmap,
                                                 const float* __restrict__ gamma,
                                                 const float* __restrict__ beta) {
    int gw   = blockIdx.x * 8 + (threadIdx.x >> 5);
    int lane = threadIdx.x & 31;
    int r = gw / NH;
    int h = gw - r * NH;
    __half2* row = (__half2*)(g_qh + (size_t)r * DIMC + h * HDIM);
    __half2 p0 = row[lane * 2], p1 = row[lane * 2 + 1];
    float4 v;
    { float2 f0 = __half22float2(p0), f1 = __half22float2(p1);
      v.x = f0.x; v.y = f0.y; v.z = f1.x; v.w = f1.y; }

    float s  = v.x + v.y + v.z + v.w;
    float sq = v.x * v.x + v.y * v.y + v.z * v.z + v.w * v.w;
    #pragma unroll
    for (int o = 16; o; o >>= 1) {
        s  += __shfl_xor_sync(0xffffffffu, s,  o);
        sq += __shfl_xor_sync(0xffffffffu, sq, o);
    }
    float mean = s * (1.f / HDIM);
    float var  = sq * (1.f / HDIM) - mean * mean;
    float rs   = rsqrtf(var + 1e-6f);

    float4 gg = *(const float4*)(gamma + lane * 4);
    float4 bb = *(const float4*)(beta  + lane * 4);
    v.x = (v.x - mean) * rs * gg.x + bb.x;
    v.y = (v.y - mean) * rs * gg.y + bb.y;
    v.z = (v.z - mean) * rs * gg.z + bb.z;
    v.w = (v.w - mean) * rs * gg.w + bb.w;

    int b = r >> 10, sidx = r & 1023;
    int l = (b * (NH * SEQ) + h * SEQ + sidx) % NTOK;
    float m0 = xmap[l], m1 = xmap[NTOK + l];
    float mn0 = g_minmax[0], mx0 = g_minmax[1], mn1 = g_minmax[2], mx1 = g_minmax[3];
    float pos = (m0 >= m1) ? (m0 - mn0) / (mx0 - mn0) * 4.0f
                           : (m1 - mn1) / (mx1 - mn1) * 4.0f + 20.0f;

    const float CF = -0.20762050593046868f;   // -2*log2(10000)/128
    int i0 = lane * 2;
    float f0 = exp2f((float)i0 * CF);
    float f1 = exp2f((float)(i0 + 1) * CF);
    float s0, c0, s1, c1;
    sincosf(pos * f0, &s0, &c0);
    sincosf(pos * f1, &s1, &c1);
    row[lane * 2]     = __floats2half2_rn(v.x * c0 - v.y * s0, v.y * c0 + v.x * s0);
    row[lane * 2 + 1] = __floats2half2_rn(v.z * c1 - v.w * s1, v.w * c1 + v.z * s1);
}

// ------------- k: LayerNorm(eps 1e-5) + RoPE (pos = 2 or 22) ---------------
__global__ __launch_bounds__(256) void k_ln_rope(const float* __restrict__ gamma,
                                                 const float* __restrict__ beta) {
    int gw   = blockIdx.x * 8 + (threadIdx.x >> 5);
    int lane = threadIdx.x & 31;
    int r = gw / NH;
    int h = gw - r * NH;
    float* row = g_KV + (size_t)r * (2 * DIMC) + h * HDIM;
    float4 v = *(float4*)(row + lane * 4);

    float s  = v.x + v.y + v.z + v.w;
    float sq = v.x * v.x + v.y * v.y + v.z * v.z + v.w * v.w;
    #pragma unroll
    for (int o = 16; o; o >>= 1) {
        s  += __shfl_xor_sync(0xffffffffu, s,  o);
        sq += __shfl_xor_sync(0xffffffffu, sq, o);
    }
    float mean = s * (1.f / HDIM);
    float var  = sq * (1.f / HDIM) - mean * mean;
    float rs   = rsqrtf(var + 1e-5f);

    float4 gg = *(const float4*)(gamma + lane * 4);
    float4 bb = *(const float4*)(beta  + lane * 4);
    v.x = (v.x - mean) * rs * gg.x + bb.x;
    v.y = (v.y - mean) * rs * gg.y + bb.y;
    v.z = (v.z - mean) * rs * gg.z + bb.z;
    v.w = (v.w - mean) * rs * gg.w + bb.w;

    int na = r & (NAK - 1);
    float pos = (na < NAK / 2) ? 2.0f : 22.0f;

    const float CF = -0.20762050593046868f;
    int i0 = lane * 2;
    float f0 = exp2f((float)i0 * CF);
    float f1 = exp2f((float)(i0 + 1) * CF);
    float s0, c0, s1, c1;
    sincosf(pos * f0, &s0, &c0);
    sincosf(pos * f1, &s1, &c1);
    float4 o;
    o.x = v.x * c0 - v.y * s0;
    o.y = v.y * c0 + v.x * s0;
    o.z = v.z * c1 - v.w * s1;
    o.w = v.w * c1 + v.z * s1;
    *(float4*)(row + lane * 4) = o;
}

// ------------- attention: per (b,h), NA=32 keys; fp16 q in, fp16 out -------
#define VPAD 132
__global__ __launch_bounds__(256) void attn_kernel() {
    int bh = blockIdx.x;
    int b = bh / NH, h = bh - b * NH;
    __shared__ float ks[NAK][VPAD], vs[NAK][VPAD];
    int tid = threadIdx.x;
    for (int idx = tid; idx < NAK * HDIM; idx += 256) {
        int n = idx >> 7, d = idx & 127;
        size_t base = (size_t)(b * NAK + n) * (2 * DIMC) + h * HDIM + d;
        ks[n][d] = g_KV[base];
        vs[n][d] = g_KV[base + DIMC];
    }
    __syncthreads();

    int warp = tid >> 5, lane = tid & 31;
    const float SC = 0.08838834764831845f;
    for (int s = warp; s < SEQ; s += 8) {
        const __half2* q = (const __half2*)(g_qh + (size_t)(b * SEQ + s) * DIMC + h * HDIM);
        float sc = 0.f;
        #pragma unroll
        for (int d = 0; d < HDIM; d += 4) {
            float2 q0 = __half22float2(q[d / 2]);
            float2 q1 = __half22float2(q[d / 2 + 1]);
            float4 kv = *(const float4*)(&ks[lane][d]);
            sc += q0.x * kv.x + q0.y * kv.y + q1.x * kv.z + q1.y * kv.w;
        }
        sc *= SC;
        float mx = sc;
        #pragma unroll
        for (int o = 16; o; o >>= 1) mx = fmaxf(mx, __shfl_xor_sync(0xffffffffu, mx, o));
        float e = __expf(sc - mx);
        float sum = e;
        #pragma unroll
        for (int o = 16; o; o >>= 1) sum += __shfl_xor_sync(0xffffffffu, sum, o);
        float p = e / sum;

        float4 acc = make_float4(0.f, 0.f, 0.f, 0.f);
        #pragma unroll
        for (int n = 0; n < NAK; n++) {
            float pn = __shfl_sync(0xffffffffu, p, n);
            float4 vv = *(const float4*)(&vs[n][lane * 4]);
            acc.x += pn * vv.x; acc.y += pn * vv.y;
            acc.z += pn * vv.z; acc.w += pn * vv.w;
        }
        __half2* op = (__half2*)(g_oh + (size_t)(b * SEQ + s) * DIMC + h * HDIM + lane * 4);
        op[0] = __floats2half2_rn(acc.x, acc.y);
        op[1] = __floats2half2_rn(acc.z, acc.w);
    }
}

// ======================= host side =======================
extern "C" void kernel_launch(void* const* d_in, const int* in_sizes, int n_in,
                              void* d_out, int out_size) {
    const float* x     = (const float*)d_in[0];
    const float* enc_i = (const float*)d_in[1];
    const float* xmap  = (const float*)d_in[2];
    const float* q_w   = (const float*)d_in[3];
    const float* q_b   = (const float*)d_in[4];
    const float* kv_w  = (const float*)d_in[5];
    const float* kv_b  = (const float*)d_in[6];
    const float* prj_w = (const float*)d_in[7];
    const float* prj_b = (const float*)d_in[8];
    const float* qn_g  = (const float*)d_in[9];
    const float* qn_b  = (const float*)d_in[10];
    const float* kn_g  = (const float*)d_in[11];
    const float* kn_b  = (const float*)d_in[12];
    float* out = (float*)d_out;

    float *KV;
    __half *qh, *xh, *oh, *eh, *wqh, *wph, *wkh;
    cudaGetSymbolAddress((void**)&KV,  g_KV);
    cudaGetSymbolAddress((void**)&qh,  g_qh);
    cudaGetSymbolAddress((void**)&xh,  g_xh);
    cudaGetSymbolAddress((void**)&oh,  g_oh);
    cudaGetSymbolAddress((void**)&eh,  g_eh);
    cudaGetSymbolAddress((void**)&wqh, g_wqh);
    cudaGetSymbolAddress((void**)&wph, g_wph);
    cudaGetSymbolAddress((void**)&wkh, g_wkh);

    cudaFuncSetAttribute(gemm_fp16<float>,  cudaFuncAttributeMaxDynamicSharedMemorySize, GEMM_SMEM);
    cudaFuncSetAttribute(gemm_fp16<__half>, cudaFuncAttributeMaxDynamicSharedMemorySize, GEMM_SMEM);

    // L1: x -> fp16
    {
        int n4 = (int)((size_t)NTOK * DIMC / 4);
        convert_single_h<<<(n4 + 255) / 256, 256>>>((const float4*)x, (__half2*)xh, n4);
    }
    // L2: enc -> fp16
    {
        int n4 = (int)((size_t)ENCR * ENCC / 4);
        convert_single_h<<<(n4 + 255) / 256, 256>>>((const float4*)enc_i, (__half2*)eh, n4);
    }
    // L3: all three weights -> fp16 (merged)
    {
        int tot = 2 * W1N + W2N;
        convert_w3<<<(tot + 255) / 256, 256>>>(
            (const float4*)q_w, (const float4*)kv_w, (const float4*)prj_w,
            (__half2*)wqh, (__half2*)wkh, (__half2*)wph);
    }
    // L4: minmax
    minmax_kernel<<<2, 256>>>(xmap);

    // L5: GEMM2  KV = enc @ kv_w^T
    gemm_fp16<float><<<dim3((2 * DIMC) / 128, (ENCR + 127) / 128), 128, GEMM_SMEM>>>(
        eh, wkh, kv_b, KV, ENCR, 2 * DIMC, ENCC);

    // L6 (ncu -s 5 captures this): GEMM1  qh = x @ q_w^T + q_b  (fp16 out)
    gemm_fp16<__half><<<dim3(DIMC / 128, NTOK / 128), 128, GEMM_SMEM>>>(
        xh, wqh, q_b, qh, NTOK, DIMC, DIMC);

    // L7: q LN + RoPE (fp16 in/out, in-place)
    ln_rope_q<<<(NTOK * NH) / 8, 256>>>(xmap, qn_g, qn_b);

    // L8: k LN + RoPE
    k_ln_rope<<<(ENCR * NH) / 8, 256>>>(kn_g, kn_b);

    // L9: attention
    attn_kernel<<<N_T * NH, 256>>>();

    // L10: GEMM3  out = attn_out @ prj_w^T
    gemm_fp16<float><<<dim3(DIMC / 128, NTOK / 128), 128, GEMM_SMEM>>>(
        oh, wph, prj_b, out, NTOK, DIMC, DIMC);
}